// round 2
// baseline (speedup 1.0000x reference)
#include <cuda_runtime.h>
#include <math.h>

#define NI 8192
#define NO 8192
#define BLOCKS (NO / 8)          // 1024 blocks, 8 rows (warps) per block
#define PREP_BLOCKS 32           // blocks 0..31 produce g_x (256 elems each)

__device__ float g_x[NI];
__device__ float g_logits[NO];
__device__ int   g_ready;        // 0 at load; reset by softmax block each run
__device__ int   g_done;

__global__ void __launch_bounds__(256)
lis_fused_kernel(const float* __restrict__ spikes,
                 const float* __restrict__ trace,
                 const float* __restrict__ decay_raw,
                 const float* __restrict__ W,
                 const float* __restrict__ bias,
                 float* __restrict__ out) {
    __shared__ float sx[NI];     // x staging; reused as exp() staging in softmax
    __shared__ float red[32];
    __shared__ int   s_last;

    const int tid  = threadIdx.x;
    const int bid  = blockIdx.x;
    const int warp = tid >> 5;
    const int lane = tid & 31;

    // ---- Phase A: blocks 0..31 compute normalized pre-trace into g_x ----
    if (bid < PREP_BLOCKS) {
        int i = bid * 256 + tid;
        float d  = 1.0f / (1.0f + expf(-decay_raw[i]));
        float nt = fmaf(trace[i], d, spikes[i]);
        g_x[i]   = nt * (1.0f - d);
        __syncthreads();
        __threadfence();
        if (tid == 0) atomicAdd(&g_ready, 1);
    }

    // ---- Wait for x to be globally visible ----
    if (tid == 0) {
        volatile int* vr = &g_ready;
        while (*vr < PREP_BLOCKS) { }
        __threadfence();
    }
    __syncthreads();

    // ---- Stage x into shared ----
    {
        const float4* gx4 = (const float4*)g_x;
        float4*       sx4 = (float4*)sx;
        for (int i = tid; i < NI / 4; i += 256)
            sx4[i] = gx4[i];
    }
    __syncthreads();

    // ---- Phase B: warp-per-row matvec (coalesced float4 stream) ----
    {
        const int row = bid * 8 + warp;
        const float4* __restrict__ wrow = (const float4*)(W + (size_t)row * NI);
        const float4* xv = (const float4*)sx;

        float acc = 0.0f;
        #pragma unroll 8
        for (int k = lane; k < NI / 4; k += 32) {
            float4 w = __ldg(&wrow[k]);
            float4 x = xv[k];
            acc = fmaf(w.x, x.x, acc);
            acc = fmaf(w.y, x.y, acc);
            acc = fmaf(w.z, x.z, acc);
            acc = fmaf(w.w, x.w, acc);
        }
        #pragma unroll
        for (int off = 16; off; off >>= 1)
            acc += __shfl_down_sync(0xffffffffu, acc, off);
        if (lane == 0)
            g_logits[row] = acc + __ldg(&bias[row]);
    }

    // ---- Elect last block ----
    __syncthreads();
    if (tid == 0) {
        __threadfence();
        int old = atomicAdd(&g_done, 1);
        s_last = (old == BLOCKS - 1) ? 1 : 0;
    }
    __syncthreads();
    if (!s_last) return;

    // ---- Phase C: softmax over 8192 logits (256 threads, 32 elems each) ----
    // Pass 1: global max
    float lmax = -INFINITY;
    for (int i = tid; i < NO; i += 256)
        lmax = fmaxf(lmax, __ldcg(&g_logits[i]));
    #pragma unroll
    for (int off = 16; off; off >>= 1)
        lmax = fmaxf(lmax, __shfl_xor_sync(0xffffffffu, lmax, off));
    if (lane == 0) red[warp] = lmax;
    __syncthreads();
    float m = (lane < 8) ? red[lane] : -INFINITY;
    #pragma unroll
    for (int off = 4; off; off >>= 1)
        m = fmaxf(m, __shfl_xor_sync(0xffffffffu, m, off));
    m = __shfl_sync(0xffffffffu, m, 0);
    __syncthreads();

    // Pass 2: exp + sum (stage exp values in sx)
    float lsum = 0.0f;
    for (int i = tid; i < NO; i += 256) {
        float e = expf(__ldcg(&g_logits[i]) - m);
        sx[i] = e;
        lsum += e;
    }
    #pragma unroll
    for (int off = 16; off; off >>= 1)
        lsum += __shfl_xor_sync(0xffffffffu, lsum, off);
    if (lane == 0) red[warp] = lsum;
    __syncthreads();
    float s = (lane < 8) ? red[lane] : 0.0f;
    #pragma unroll
    for (int off = 4; off; off >>= 1)
        s += __shfl_xor_sync(0xffffffffu, s, off);
    s = __shfl_sync(0xffffffffu, s, 0);

    // Pass 3: normalize and write out
    const float inv = 1.0f / s;
    for (int i = tid; i < NO; i += 256)
        out[i] = sx[i] * inv;

    // ---- Reset counters for next graph replay ----
    __syncthreads();
    if (tid == 0) {
        g_ready = 0;
        g_done  = 0;
        __threadfence();
    }
}

extern "C" void kernel_launch(void* const* d_in, const int* in_sizes, int n_in,
                              void* d_out, int out_size) {
    const float* in_spikes     = (const float*)d_in[0];
    const float* pre_trace     = (const float*)d_in[1];
    const float* weight        = (const float*)d_in[2];
    const float* bias          = (const float*)d_in[3];
    const float* pre_decay_raw = (const float*)d_in[4];
    float* out = (float*)d_out;

    lis_fused_kernel<<<BLOCKS, 256>>>(in_spikes, pre_trace, pre_decay_raw,
                                      weight, bias, out);
}

// round 3
// speedup vs baseline: 1.1431x; 1.1431x over previous
#include <cuda_runtime.h>
#include <math.h>

#define NI 8192
#define NO 8192
#define TPB 256
#define NB  512                      // 512 blocks x 8 warps = 4096 warps
#define WARPS_TOTAL (NB * 8)         // each warp: rows gw and gw+4096
#define PREP_BLOCKS 32

__device__ float g_x[NI];
__device__ float g_logits[NO];
__device__ volatile int g_ready;     // zero-init; reset by elected block
__device__ int g_done;

__global__ void __launch_bounds__(TPB)
lis_fused(const float* __restrict__ spikes,
          const float* __restrict__ trace,
          const float* __restrict__ decay_raw,
          const float* __restrict__ W,
          const float* __restrict__ bias,
          float* __restrict__ out) {
    __shared__ float sx[NI];         // 32KB: x staging; exp staging in softmax
    __shared__ float red[32];
    __shared__ int   s_last;

    const int tid  = threadIdx.x;
    const int bid  = blockIdx.x;
    const int warp = tid >> 5;
    const int lane = tid & 31;
    const int gw   = bid * 8 + warp;
    const int r0   = gw;
    const int r1   = gw + WARPS_TOTAL;

    const float4* __restrict__ wa = (const float4*)(W + (size_t)r0 * NI);
    const float4* __restrict__ wb = (const float4*)(W + (size_t)r1 * NI);

    // ---- Prefetch first chunk of both rows BEFORE the sync (hides prep) ----
    float4 pa0 = __ldcs(wa + lane);
    float4 pa1 = __ldcs(wa + lane + 32);
    float4 pb0 = __ldcs(wb + lane);
    float4 pb1 = __ldcs(wb + lane + 32);

    // ---- Phase A: blocks 0..31 produce normalized pre-trace ----
    if (bid < PREP_BLOCKS) {
        int i = bid * TPB + tid;
        float d  = 1.0f / (1.0f + __expf(-decay_raw[i]));
        float nt = fmaf(trace[i], d, spikes[i]);
        g_x[i]   = nt * (1.0f - d);
        __threadfence();
        __syncthreads();
        if (tid == 0) atomicAdd((int*)&g_ready, 1);
    }

    // ---- Wait until x is globally complete ----
    if (tid == 0) {
        while (g_ready < PREP_BLOCKS) { }
        __threadfence();
    }
    __syncthreads();

    // ---- Stage x into shared (fresh from L2) ----
    {
        const float4* gx4 = (const float4*)g_x;
        float4*       sx4 = (float4*)sx;
        for (int i = tid; i < NI / 4; i += TPB)
            sx4[i] = __ldcg(gx4 + i);
    }
    __syncthreads();

    // ---- Phase B: dual-row matvec, 4 independent streams per warp ----
    const float4* xv = (const float4*)sx;
    float a0, a1, b0, b1;
    {
        float4 x0 = xv[lane];
        float4 x1 = xv[lane + 32];
        a0 = pa0.x*x0.x + pa0.y*x0.y + pa0.z*x0.z + pa0.w*x0.w;
        a1 = pa1.x*x1.x + pa1.y*x1.y + pa1.z*x1.z + pa1.w*x1.w;
        b0 = pb0.x*x0.x + pb0.y*x0.y + pb0.z*x0.z + pb0.w*x0.w;
        b1 = pb1.x*x1.x + pb1.y*x1.y + pb1.z*x1.z + pb1.w*x1.w;
    }
    for (int k = lane + 64; k < NI / 4; k += 64) {
        float4 wa0 = __ldcs(wa + k);
        float4 wa1 = __ldcs(wa + k + 32);
        float4 wb0 = __ldcs(wb + k);
        float4 wb1 = __ldcs(wb + k + 32);
        float4 x0  = xv[k];
        float4 x1  = xv[k + 32];
        a0 = fmaf(wa0.x, x0.x, a0); a0 = fmaf(wa0.y, x0.y, a0);
        a0 = fmaf(wa0.z, x0.z, a0); a0 = fmaf(wa0.w, x0.w, a0);
        a1 = fmaf(wa1.x, x1.x, a1); a1 = fmaf(wa1.y, x1.y, a1);
        a1 = fmaf(wa1.z, x1.z, a1); a1 = fmaf(wa1.w, x1.w, a1);
        b0 = fmaf(wb0.x, x0.x, b0); b0 = fmaf(wb0.y, x0.y, b0);
        b0 = fmaf(wb0.z, x0.z, b0); b0 = fmaf(wb0.w, x0.w, b0);
        b1 = fmaf(wb1.x, x1.x, b1); b1 = fmaf(wb1.y, x1.y, b1);
        b1 = fmaf(wb1.z, x1.z, b1); b1 = fmaf(wb1.w, x1.w, b1);
    }
    float accA = a0 + a1;
    float accB = b0 + b1;
    #pragma unroll
    for (int off = 16; off; off >>= 1) {
        accA += __shfl_down_sync(0xffffffffu, accA, off);
        accB += __shfl_down_sync(0xffffffffu, accB, off);
    }
    if (lane == 0) {
        g_logits[r0] = accA + __ldg(&bias[r0]);
        g_logits[r1] = accB + __ldg(&bias[r1]);
    }

    // ---- Elect last block ----
    __threadfence();
    __syncthreads();
    if (tid == 0) {
        int old = atomicAdd(&g_done, 1);
        s_last = (old == NB - 1) ? 1 : 0;
    }
    __syncthreads();
    if (!s_last) return;
    __threadfence();

    // ---- Phase C: softmax (256 threads, exp staged in sx) ----
    float lmax = -INFINITY;
    for (int i = tid; i < NO; i += TPB)
        lmax = fmaxf(lmax, __ldcg(&g_logits[i]));
    #pragma unroll
    for (int off = 16; off; off >>= 1)
        lmax = fmaxf(lmax, __shfl_xor_sync(0xffffffffu, lmax, off));
    if (lane == 0) red[warp] = lmax;
    __syncthreads();
    float m = (lane < 8) ? red[lane] : -INFINITY;
    #pragma unroll
    for (int off = 4; off; off >>= 1)
        m = fmaxf(m, __shfl_xor_sync(0xffffffffu, m, off));
    m = __shfl_sync(0xffffffffu, m, 0);
    __syncthreads();

    float lsum = 0.0f;
    for (int i = tid; i < NO; i += TPB) {
        float e = __expf(__ldcg(&g_logits[i]) - m);
        sx[i] = e;
        lsum += e;
    }
    #pragma unroll
    for (int off = 16; off; off >>= 1)
        lsum += __shfl_xor_sync(0xffffffffu, lsum, off);
    if (lane == 0) red[warp] = lsum;
    __syncthreads();
    float s = (lane < 8) ? red[lane] : 0.0f;
    #pragma unroll
    for (int off = 4; off; off >>= 1)
        s += __shfl_xor_sync(0xffffffffu, s, off);
    s = __shfl_sync(0xffffffffu, s, 0);

    const float inv = 1.0f / s;
    for (int i = tid; i < NO; i += TPB)
        out[i] = sx[i] * inv;

    // ---- Reset counters for next graph replay ----
    __syncthreads();
    if (tid == 0) {
        g_ready = 0;
        g_done  = 0;
        __threadfence();
    }
}

extern "C" void kernel_launch(void* const* d_in, const int* in_sizes, int n_in,
                              void* d_out, int out_size) {
    const float* in_spikes     = (const float*)d_in[0];
    const float* pre_trace     = (const float*)d_in[1];
    const float* weight        = (const float*)d_in[2];
    const float* bias          = (const float*)d_in[3];
    const float* pre_decay_raw = (const float*)d_in[4];
    float* out = (float*)d_out;

    lis_fused<<<NB, TPB>>>(in_spikes, pre_trace, pre_decay_raw,
                           weight, bias, out);
}

// round 4
// speedup vs baseline: 1.1483x; 1.0046x over previous
#include <cuda_runtime.h>
#include <math.h>

#define NI 8192
#define NO 8192
#define TPB 256
#define NB  512                      // 512 blocks x 8 warps = 4096 warps
#define WARPS_TOTAL (NB * 8)         // each warp: rows gw and gw+4096
#define PREP_BLOCKS 32

__device__ float g_x[NI];
__device__ float g_logits[NO];
__device__ volatile int g_ready;     // zero-init; reset by elected block
__device__ int g_done;

__global__ void __launch_bounds__(TPB, 4)
lis_fused(const float* __restrict__ spikes,
          const float* __restrict__ trace,
          const float* __restrict__ decay_raw,
          const float* __restrict__ W,
          const float* __restrict__ bias,
          float* __restrict__ out) {
    __shared__ float sx[NI];         // 32KB: x staging; exp staging in softmax
    __shared__ float red[32];
    __shared__ int   s_last;

    const int tid  = threadIdx.x;
    const int bid  = blockIdx.x;
    const int warp = tid >> 5;
    const int lane = tid & 31;
    const int gw   = bid * 8 + warp;
    const int r0   = gw;
    const int r1   = gw + WARPS_TOTAL;

    const float4* __restrict__ wa = (const float4*)(W + (size_t)r0 * NI);
    const float4* __restrict__ wb = (const float4*)(W + (size_t)r1 * NI);

    // ---- Prefetch full first iteration (8x LDG.128) BEFORE the sync ----
    float4 pa0 = __ldcs(wa + lane);
    float4 pa1 = __ldcs(wa + lane + 32);
    float4 pa2 = __ldcs(wa + lane + 64);
    float4 pa3 = __ldcs(wa + lane + 96);
    float4 pb0 = __ldcs(wb + lane);
    float4 pb1 = __ldcs(wb + lane + 32);
    float4 pb2 = __ldcs(wb + lane + 64);
    float4 pb3 = __ldcs(wb + lane + 96);

    // ---- Phase A: blocks 0..31 produce normalized pre-trace ----
    if (bid < PREP_BLOCKS) {
        int i = bid * TPB + tid;
        float d  = 1.0f / (1.0f + __expf(-decay_raw[i]));
        float nt = fmaf(trace[i], d, spikes[i]);
        g_x[i]   = nt * (1.0f - d);
        __threadfence();
        __syncthreads();
        if (tid == 0) atomicAdd((int*)&g_ready, 1);
    }

    // ---- Wait until x is globally complete ----
    if (tid == 0) {
        while (g_ready < PREP_BLOCKS) { }
        __threadfence();
    }
    __syncthreads();

    // ---- Stage x into shared ----
    {
        const float4* gx4 = (const float4*)g_x;
        float4*       sx4 = (float4*)sx;
        for (int i = tid; i < NI / 4; i += TPB)
            sx4[i] = __ldcg(gx4 + i);
    }
    __syncthreads();

    // ---- Phase B: dual-row matvec, 8 independent LDG.128 streams ----
    const float4* xv = (const float4*)sx;
    float aA0, aA1, aA2, aA3, aB0, aB1, aB2, aB3;
    {
        float4 x0 = xv[lane];
        aA0 = pa0.x*x0.x + pa0.y*x0.y + pa0.z*x0.z + pa0.w*x0.w;
        aB0 = pb0.x*x0.x + pb0.y*x0.y + pb0.z*x0.z + pb0.w*x0.w;
        float4 x1 = xv[lane + 32];
        aA1 = pa1.x*x1.x + pa1.y*x1.y + pa1.z*x1.z + pa1.w*x1.w;
        aB1 = pb1.x*x1.x + pb1.y*x1.y + pb1.z*x1.z + pb1.w*x1.w;
        float4 x2 = xv[lane + 64];
        aA2 = pa2.x*x2.x + pa2.y*x2.y + pa2.z*x2.z + pa2.w*x2.w;
        aB2 = pb2.x*x2.x + pb2.y*x2.y + pb2.z*x2.z + pb2.w*x2.w;
        float4 x3 = xv[lane + 96];
        aA3 = pa3.x*x3.x + pa3.y*x3.y + pa3.z*x3.z + pa3.w*x3.w;
        aB3 = pb3.x*x3.x + pb3.y*x3.y + pb3.z*x3.z + pb3.w*x3.w;
    }
    #pragma unroll 1
    for (int k = lane + 128; k < NI / 4; k += 128) {
        float4 wa0 = __ldcs(wa + k);
        float4 wa1 = __ldcs(wa + k + 32);
        float4 wa2 = __ldcs(wa + k + 64);
        float4 wa3 = __ldcs(wa + k + 96);
        float4 wb0 = __ldcs(wb + k);
        float4 wb1 = __ldcs(wb + k + 32);
        float4 wb2 = __ldcs(wb + k + 64);
        float4 wb3 = __ldcs(wb + k + 96);

        float4 x0 = xv[k];
        aA0 = fmaf(wa0.x, x0.x, aA0); aA0 = fmaf(wa0.y, x0.y, aA0);
        aA0 = fmaf(wa0.z, x0.z, aA0); aA0 = fmaf(wa0.w, x0.w, aA0);
        aB0 = fmaf(wb0.x, x0.x, aB0); aB0 = fmaf(wb0.y, x0.y, aB0);
        aB0 = fmaf(wb0.z, x0.z, aB0); aB0 = fmaf(wb0.w, x0.w, aB0);
        float4 x1 = xv[k + 32];
        aA1 = fmaf(wa1.x, x1.x, aA1); aA1 = fmaf(wa1.y, x1.y, aA1);
        aA1 = fmaf(wa1.z, x1.z, aA1); aA1 = fmaf(wa1.w, x1.w, aA1);
        aB1 = fmaf(wb1.x, x1.x, aB1); aB1 = fmaf(wb1.y, x1.y, aB1);
        aB1 = fmaf(wb1.z, x1.z, aB1); aB1 = fmaf(wb1.w, x1.w, aB1);
        float4 x2 = xv[k + 64];
        aA2 = fmaf(wa2.x, x2.x, aA2); aA2 = fmaf(wa2.y, x2.y, aA2);
        aA2 = fmaf(wa2.z, x2.z, aA2); aA2 = fmaf(wa2.w, x2.w, aA2);
        aB2 = fmaf(wb2.x, x2.x, aB2); aB2 = fmaf(wb2.y, x2.y, aB2);
        aB2 = fmaf(wb2.z, x2.z, aB2); aB2 = fmaf(wb2.w, x2.w, aB2);
        float4 x3 = xv[k + 96];
        aA3 = fmaf(wa3.x, x3.x, aA3); aA3 = fmaf(wa3.y, x3.y, aA3);
        aA3 = fmaf(wa3.z, x3.z, aA3); aA3 = fmaf(wa3.w, x3.w, aA3);
        aB3 = fmaf(wb3.x, x3.x, aB3); aB3 = fmaf(wb3.y, x3.y, aB3);
        aB3 = fmaf(wb3.z, x3.z, aB3); aB3 = fmaf(wb3.w, x3.w, aB3);
    }
    float accA = (aA0 + aA1) + (aA2 + aA3);
    float accB = (aB0 + aB1) + (aB2 + aB3);
    #pragma unroll
    for (int off = 16; off; off >>= 1) {
        accA += __shfl_down_sync(0xffffffffu, accA, off);
        accB += __shfl_down_sync(0xffffffffu, accB, off);
    }
    if (lane == 0) {
        g_logits[r0] = accA + __ldg(&bias[r0]);
        g_logits[r1] = accB + __ldg(&bias[r1]);
    }

    // ---- Elect last block ----
    __threadfence();
    __syncthreads();
    if (tid == 0) {
        int old = atomicAdd(&g_done, 1);
        s_last = (old == NB - 1) ? 1 : 0;
    }
    __syncthreads();
    if (!s_last) return;
    __threadfence();

    // ---- Phase C: softmax (256 threads, exp staged in sx) ----
    float lmax = -INFINITY;
    for (int i = tid; i < NO; i += TPB)
        lmax = fmaxf(lmax, __ldcg(&g_logits[i]));
    #pragma unroll
    for (int off = 16; off; off >>= 1)
        lmax = fmaxf(lmax, __shfl_xor_sync(0xffffffffu, lmax, off));
    if (lane == 0) red[warp] = lmax;
    __syncthreads();
    float m = (lane < 8) ? red[lane] : -INFINITY;
    #pragma unroll
    for (int off = 4; off; off >>= 1)
        m = fmaxf(m, __shfl_xor_sync(0xffffffffu, m, off));
    m = __shfl_sync(0xffffffffu, m, 0);
    __syncthreads();

    float lsum = 0.0f;
    for (int i = tid; i < NO; i += TPB) {
        float e = __expf(__ldcg(&g_logits[i]) - m);
        sx[i] = e;
        lsum += e;
    }
    #pragma unroll
    for (int off = 16; off; off >>= 1)
        lsum += __shfl_xor_sync(0xffffffffu, lsum, off);
    if (lane == 0) red[warp] = lsum;
    __syncthreads();
    float s = (lane < 8) ? red[lane] : 0.0f;
    #pragma unroll
    for (int off = 4; off; off >>= 1)
        s += __shfl_xor_sync(0xffffffffu, s, off);
    s = __shfl_sync(0xffffffffu, s, 0);

    const float inv = 1.0f / s;
    for (int i = tid; i < NO; i += TPB)
        out[i] = sx[i] * inv;

    // ---- Reset counters for next graph replay ----
    __syncthreads();
    if (tid == 0) {
        g_ready = 0;
        g_done  = 0;
        __threadfence();
    }
}

extern "C" void kernel_launch(void* const* d_in, const int* in_sizes, int n_in,
                              void* d_out, int out_size) {
    const float* in_spikes     = (const float*)d_in[0];
    const float* pre_trace     = (const float*)d_in[1];
    const float* weight        = (const float*)d_in[2];
    const float* bias          = (const float*)d_in[3];
    const float* pre_decay_raw = (const float*)d_in[4];
    float* out = (float*)d_out;

    lis_fused<<<NB, TPB>>>(in_spikes, pre_trace, pre_decay_raw,
                           weight, bias, out);
}

// round 6
// speedup vs baseline: 1.2090x; 1.0529x over previous
#include <cuda_runtime.h>
#include <stdint.h>
#include <math.h>

#define NI 8192
#define NO 8192
#define TPB 256
#define NB  512                       // 512 blocks x 8 warps = 4096 warps
#define WARPS_TOTAL (NB * 8)          // each warp: rows gw and gw+4096
#define PREP_BLOCKS 32

#define CHUNK  128                    // floats per chunk per row (512B)
#define NCHUNK (NI / CHUNK)           // 64 chunks
#define STAGES 5                      // smem ring depth

__device__ float g_x[NI];
__device__ float g_logits[NO];
__device__ volatile int g_ready;
__device__ int g_done;

__global__ void __launch_bounds__(TPB, 4)
lis_fused(const float* __restrict__ spikes,
          const float* __restrict__ trace,
          const float* __restrict__ decay_raw,
          const float* __restrict__ W,
          const float* __restrict__ bias,
          float* __restrict__ out) {
    // [stage][local row (16 = 8 warps * 2 rows)][CHUNK floats] = 40KB
    __shared__ __align__(16) float sW[STAGES][16][CHUNK];
    __shared__ float red[32];
    __shared__ int   s_last;

    const int tid  = threadIdx.x;
    const int bid  = blockIdx.x;
    const int warp = tid >> 5;
    const int lane = tid & 31;
    const int gw   = bid * 8 + warp;
    const int r0   = gw;
    const int r1   = gw + WARPS_TOTAL;

    const float* __restrict__ wa = W + (size_t)r0 * NI;
    const float* __restrict__ wb = W + (size_t)r1 * NI;

    const unsigned swb = (unsigned)__cvta_generic_to_shared(&sW[0][0][0]);
    const unsigned lane_off = (unsigned)(lane * 4 * 4);        // lane*4 floats
    const unsigned row0_off = (unsigned)((2 * warp)     * CHUNK * 4);
    const unsigned row1_off = (unsigned)((2 * warp + 1) * CHUNK * 4);
    const unsigned stage_bytes = 16 * CHUNK * 4;               // 8KB per stage

    // ---- Prologue: fill all STAGES stages (issued BEFORE prep/spin) ----
    #pragma unroll
    for (int s = 0; s < STAGES; ++s) {
        const float* s0 = wa + s * CHUNK + lane * 4;
        const float* s1 = wb + s * CHUNK + lane * 4;
        unsigned d0 = swb + s * stage_bytes + row0_off + lane_off;
        unsigned d1 = swb + s * stage_bytes + row1_off + lane_off;
        asm volatile("cp.async.cg.shared.global [%0], [%1], 16;" :: "r"(d0), "l"(s0) : "memory");
        asm volatile("cp.async.cg.shared.global [%0], [%1], 16;" :: "r"(d1), "l"(s1) : "memory");
        asm volatile("cp.async.commit_group;" ::: "memory");
    }

    // ---- Phase A: blocks 0..31 produce normalized pre-trace ----
    if (bid < PREP_BLOCKS) {
        int i = bid * TPB + tid;
        float d  = 1.0f / (1.0f + __expf(-decay_raw[i]));
        float nt = fmaf(trace[i], d, spikes[i]);
        g_x[i]   = nt * (1.0f - d);
        __threadfence();
        __syncthreads();
        if (tid == 0) atomicAdd((int*)&g_ready, 1);
    }

    // ---- Wait until x is globally complete ----
    if (tid == 0) {
        while (g_ready < PREP_BLOCKS) { }
        __threadfence();
    }
    __syncthreads();

    // ---- Phase B: warp-private cp.async pipeline over 64 chunks ----
    float acc0 = 0.0f, acc1 = 0.0f;
    int st = 0;
    int i  = 0;
    #pragma unroll 1
    for (; i < NCHUNK - STAGES; ++i) {
        asm volatile("cp.async.wait_group %0;" :: "n"(STAGES - 1) : "memory");

        // consume stage st (each lane reads exactly the bytes it fetched)
        float4 w0 = *(const float4*)&sW[st][2 * warp][lane * 4];
        float4 w1 = *(const float4*)&sW[st][2 * warp + 1][lane * 4];
        float4 xv = __ldg((const float4*)(g_x + i * CHUNK + lane * 4));
        acc0 = fmaf(w0.x, xv.x, acc0); acc0 = fmaf(w0.y, xv.y, acc0);
        acc0 = fmaf(w0.z, xv.z, acc0); acc0 = fmaf(w0.w, xv.w, acc0);
        acc1 = fmaf(w1.x, xv.x, acc1); acc1 = fmaf(w1.y, xv.y, acc1);
        acc1 = fmaf(w1.z, xv.z, acc1); acc1 = fmaf(w1.w, xv.w, acc1);

        // refill stage st with chunk i+STAGES
        {
            int c = i + STAGES;
            const float* s0 = wa + c * CHUNK + lane * 4;
            const float* s1 = wb + c * CHUNK + lane * 4;
            unsigned d0 = swb + st * stage_bytes + row0_off + lane_off;
            unsigned d1 = swb + st * stage_bytes + row1_off + lane_off;
            asm volatile("cp.async.cg.shared.global [%0], [%1], 16;" :: "r"(d0), "l"(s0) : "memory");
            asm volatile("cp.async.cg.shared.global [%0], [%1], 16;" :: "r"(d1), "l"(s1) : "memory");
            asm volatile("cp.async.commit_group;" ::: "memory");
        }
        st = (st + 1 == STAGES) ? 0 : st + 1;
    }
    // drain tail
    asm volatile("cp.async.wait_group 0;" ::: "memory");
    #pragma unroll
    for (; i < NCHUNK; ++i) {
        float4 w0 = *(const float4*)&sW[st][2 * warp][lane * 4];
        float4 w1 = *(const float4*)&sW[st][2 * warp + 1][lane * 4];
        float4 xv = __ldg((const float4*)(g_x + i * CHUNK + lane * 4));
        acc0 = fmaf(w0.x, xv.x, acc0); acc0 = fmaf(w0.y, xv.y, acc0);
        acc0 = fmaf(w0.z, xv.z, acc0); acc0 = fmaf(w0.w, xv.w, acc0);
        acc1 = fmaf(w1.x, xv.x, acc1); acc1 = fmaf(w1.y, xv.y, acc1);
        acc1 = fmaf(w1.z, xv.z, acc1); acc1 = fmaf(w1.w, xv.w, acc1);
        st = (st + 1 == STAGES) ? 0 : st + 1;
    }

    #pragma unroll
    for (int off = 16; off; off >>= 1) {
        acc0 += __shfl_down_sync(0xffffffffu, acc0, off);
        acc1 += __shfl_down_sync(0xffffffffu, acc1, off);
    }
    if (lane == 0) {
        g_logits[r0] = acc0 + __ldg(&bias[r0]);
        g_logits[r1] = acc1 + __ldg(&bias[r1]);
    }

    // ---- Elect last block ----
    __threadfence();
    __syncthreads();
    if (tid == 0) {
        int old = atomicAdd(&g_done, 1);
        s_last = (old == NB - 1) ? 1 : 0;
    }
    __syncthreads();
    if (!s_last) return;
    __threadfence();

    // ---- Phase C: softmax (exp staged in sW, reused as flat buffer) ----
    float* sflat = &sW[0][0][0];
    float lmax = -INFINITY;
    for (int k = tid; k < NO; k += TPB)
        lmax = fmaxf(lmax, __ldcg(&g_logits[k]));
    #pragma unroll
    for (int off = 16; off; off >>= 1)
        lmax = fmaxf(lmax, __shfl_xor_sync(0xffffffffu, lmax, off));
    if (lane == 0) red[warp] = lmax;
    __syncthreads();
    float m = (lane < 8) ? red[lane] : -INFINITY;
    #pragma unroll
    for (int off = 4; off; off >>= 1)
        m = fmaxf(m, __shfl_xor_sync(0xffffffffu, m, off));
    m = __shfl_sync(0xffffffffu, m, 0);
    __syncthreads();

    float lsum = 0.0f;
    for (int k = tid; k < NO; k += TPB) {
        float e = __expf(__ldcg(&g_logits[k]) - m);
        sflat[k] = e;
        lsum += e;
    }
    #pragma unroll
    for (int off = 16; off; off >>= 1)
        lsum += __shfl_xor_sync(0xffffffffu, lsum, off);
    if (lane == 0) red[warp] = lsum;
    __syncthreads();
    float s = (lane < 8) ? red[lane] : 0.0f;
    #pragma unroll
    for (int off = 4; off; off >>= 1)
        s += __shfl_xor_sync(0xffffffffu, s, off);
    s = __shfl_sync(0xffffffffu, s, 0);

    const float inv = 1.0f / s;
    for (int k = tid; k < NO; k += TPB)
        out[k] = sflat[k] * inv;

    // ---- Reset counters for next graph replay ----
    __syncthreads();
    if (tid == 0) {
        g_ready = 0;
        g_done  = 0;
        __threadfence();
    }
}

extern "C" void kernel_launch(void* const* d_in, const int* in_sizes, int n_in,
                              void* d_out, int out_size) {
    const float* in_spikes     = (const float*)d_in[0];
    const float* pre_trace     = (const float*)d_in[1];
    const float* weight        = (const float*)d_in[2];
    const float* bias          = (const float*)d_in[3];
    const float* pre_decay_raw = (const float*)d_in[4];
    float* out = (float*)d_out;

    lis_fused<<<NB, TPB>>>(in_spikes, pre_trace, pre_decay_raw,
                           weight, bias, out);
}